// round 11
// baseline (speedup 1.0000x reference)
#include <cuda_runtime.h>
#include <cuda_bf16.h>
#include <cstdint>

#define NPL   16384
#define NLVL  8
#define EPL   (NPL * 8)
#define TM    128
#define NB    128
#define NT    512
#define PITCHA 72           // bf16 elems per A row (144 B) -> conflict-free ldmatrix

// smem byte offsets
#define OFF_AHI 0                        // 128 x 72 bf16 = 18432 B
#define OFF_ALO 18432
#define OFF_BPK 36864                    // 4 mats x 4 ksteps x 8 ntiles x 32 x uint2 = 32768 B
#define OFF_BL  69632                    // 64 floats
#define OFF_IDX 69888                    // 2 x 4096 B index double buffer
#define SMEM_BYTES (OFF_IDX + 8192)      // 78080 B

__device__ unsigned int g_count = 0;
__device__ unsigned int g_phase = 0;

__device__ __forceinline__ void grid_barrier() {
    __threadfence();
    __syncthreads();
    if (threadIdx.x == 0) {
        volatile unsigned int* ph = &g_phase;
        unsigned int my = *ph;
        unsigned int v = atomicAdd(&g_count, 1u);
        if (v == NB - 1) {
            atomicExch(&g_count, 0u);
            __threadfence();
            atomicAdd(&g_phase, 1u);
        } else {
            while (*ph == my) { }
        }
    }
    __syncthreads();
}

__device__ __forceinline__ float tanh_fast(float v) {
    v = fminf(fmaxf(v, -20.0f), 20.0f);
    float e;
    asm("ex2.approx.f32 %0, %1;" : "=f"(e) : "f"(v * 2.8853900817779268f)); // exp(2v)
    float r;
    asm("rcp.approx.f32 %0, %1;" : "=f"(r) : "f"(e + 1.0f));
    return (e - 1.0f) * r;
}

__device__ __forceinline__ uint32_t smem_u32(const void* p) {
    uint32_t a;
    asm("{ .reg .u64 t; cvta.to.shared.u64 t, %1; cvt.u32.u64 %0, t; }" : "=r"(a) : "l"(p));
    return a;
}

__device__ __forceinline__ void split2(float a0, float a1, uint32_t& hi, uint32_t& lo) {
    __nv_bfloat162 h = __floats2bfloat162_rn(a0, a1);
    hi = *reinterpret_cast<uint32_t*>(&h);
    float r0 = a0 - __bfloat162float(h.x);
    float r1 = a1 - __bfloat162float(h.y);
    __nv_bfloat162 l = __floats2bfloat162_rn(r0, r1);
    lo = *reinterpret_cast<uint32_t*>(&l);
}

#define CP_ASYNC16(saddr, gptr) \
    asm volatile("cp.async.cg.shared.global [%0], [%1], 16;" :: "r"(saddr), "l"(gptr))

#define LDSM4(a0, a1, a2, a3, addr)                                              \
    asm volatile("ldmatrix.sync.aligned.m8n8.x4.shared.b16 {%0,%1,%2,%3}, [%4];" \
                 : "=r"(a0), "=r"(a1), "=r"(a2), "=r"(a3) : "r"(addr))

#define MMA(accj, a0, a1, a2, a3, b0, b1)                                        \
    asm volatile("mma.sync.aligned.m16n8k16.row.col.f32.bf16.bf16.f32 "          \
                 "{%0,%1,%2,%3}, {%4,%5,%6,%7}, {%8,%9}, {%0,%1,%2,%3};"         \
                 : "+f"(accj[0]), "+f"(accj[1]), "+f"(accj[2]), "+f"(accj[3])    \
                 : "r"(a0), "r"(a1), "r"(a2), "r"(a3), "r"(b0), "r"(b1))

// One k-step, all 3 split terms, shared LDSM + B-fragment loads.
// mhi/mlo select the hi/lo fragment sets (0/1 = W_r, 2/3 = W_l).
#define MMA_KSTEP(s, mhi, mlo) do {                                              \
    uint32_t ah0, ah1, ah2, ah3, al0, al1, al2, al3;                             \
    LDSM4(ah0, ah1, ah2, ah3, aHiBase + (uint32_t)(s) * 32u);                    \
    LDSM4(al0, al1, al2, al3, aLoBase + (uint32_t)(s) * 32u);                    \
    const uint2* bph = Bpk + (((size_t)(mhi) * 4 + (s)) * 8 + 4 * ng) * 32 + lane; \
    const uint2* bpl = Bpk + (((size_t)(mlo) * 4 + (s)) * 8 + 4 * ng) * 32 + lane; \
    uint2 bh0 = bph[0], bh1 = bph[32], bh2 = bph[64], bh3 = bph[96];             \
    uint2 bl0 = bpl[0], bl1 = bpl[32], bl2 = bpl[64], bl3 = bpl[96];             \
    MMA(acc[0], ah0, ah1, ah2, ah3, bh0.x, bh0.y);                               \
    MMA(acc[1], ah0, ah1, ah2, ah3, bh1.x, bh1.y);                               \
    MMA(acc[2], ah0, ah1, ah2, ah3, bh2.x, bh2.y);                               \
    MMA(acc[3], ah0, ah1, ah2, ah3, bh3.x, bh3.y);                               \
    MMA(acc[0], ah0, ah1, ah2, ah3, bl0.x, bl0.y);                               \
    MMA(acc[1], ah0, ah1, ah2, ah3, bl1.x, bl1.y);                               \
    MMA(acc[2], ah0, ah1, ah2, ah3, bl2.x, bl2.y);                               \
    MMA(acc[3], ah0, ah1, ah2, ah3, bl3.x, bl3.y);                               \
    MMA(acc[0], al0, al1, al2, al3, bh0.x, bh0.y);                               \
    MMA(acc[1], al0, al1, al2, al3, bh1.x, bh1.y);                               \
    MMA(acc[2], al0, al1, al2, al3, bh2.x, bh2.y);                               \
    MMA(acc[3], al0, al1, al2, al3, bh3.x, bh3.y);                               \
} while (0)

__global__ void __launch_bounds__(NT, 1)
dag_mma(const float* __restrict__ x,
        const int*   __restrict__ src,
        const float* __restrict__ Wl,
        const float* __restrict__ bl,
        const float* __restrict__ Wr,
        float*       __restrict__ out)
{
    extern __shared__ char smem[];
    __nv_bfloat16* Ahi  = (__nv_bfloat16*)(smem + OFF_AHI);
    __nv_bfloat16* Alo  = (__nv_bfloat16*)(smem + OFF_ALO);
    const uint2*   Bpk  = (const uint2*)(smem + OFF_BPK);
    uint2*         BpkW = (uint2*)(smem + OFF_BPK);
    float*         bls  = (float*)(smem + OFF_BL);
    const uint32_t sb   = smem_u32(smem);

    const int t    = threadIdx.x;
    const int b    = blockIdx.x;
    const int lane = t & 31;
    const int w    = t >> 5;
    const int tig  = lane & 3;
    const int g    = lane >> 2;
    const int mg   = w >> 1;        // rows 16mg..16mg+15
    const int ng   = w & 1;         // cols 32ng..32ng+31

    // ---- one-time: prepack fragment sets {Wr_hi, Wr_lo, Wl_hi, Wl_lo} + bias ----
    {
        #pragma unroll
        for (int it = 0; it < 8; it++) {
            int idx  = t + it * NT;          // 0..4095
            int ln   = idx & 31;
            int tile = idx >> 5;             // 0..127
            int mat  = tile >> 5;            // 0..3
            int s    = (tile >> 3) & 3;      // kstep 0..3
            int j    = tile & 7;             // n-tile 0..7
            int n    = 8 * j + (ln >> 2);
            int k0   = 16 * s + 2 * (ln & 3);
            const float* W = (mat < 2) ? Wr : Wl;
            float v00 = W[n * 64 + k0],     v01 = W[n * 64 + k0 + 1];
            float v10 = W[n * 64 + k0 + 8], v11 = W[n * 64 + k0 + 9];
            uint32_t h0, l0, h1, l1;
            split2(v00, v01, h0, l0);
            split2(v10, v11, h1, l1);
            BpkW[(size_t)tile * 32 + ln] = (mat & 1) ? make_uint2(l0, l1) : make_uint2(h0, h1);
        }
        if (t < 64) bls[t] = bl[t];
    }

    // ---- prefetch level-1 edge indices ----
    if (t < 256) {
        const char* gp = (const char*)(src + (size_t)b * TM * 8) + t * 16;
        CP_ASYNC16(sb + OFF_IDX + 4096 + t * 16, gp);
    }
    asm volatile("cp.async.commit_group;" ::: "memory");

    const int row_l = lane & 15;
    const int kof   = (lane >> 4) << 3;
    const uint32_t aHiBase = sb + OFF_AHI + (uint32_t)((16 * mg + row_l) * PITCHA + kof) * 2u;
    const uint32_t aLoBase = sb + OFF_ALO + (uint32_t)((16 * mg + row_l) * PITCHA + kof) * 2u;

    // =================== PHASE 1: out[r] = x[r] @ W_r^T for ALL rows ===================
    // Block b, tile i covers rows (i*NB + b)*TM .. +127  == exactly the rows this
    // block processes at level i. Level 0's value is final; levels 1..7 hold xWr
    // until phase 2 finalizes them (same thread writes & later reads each element).
    {
        float px[16];
        {   // load tile 0
            const float* xb = x + (size_t)(b * TM) * 64;
            #pragma unroll
            for (int it = 0; it < 8; it++) {
                int idx = t + it * NT;
                int r = idx >> 5, c = (idx & 31) * 2;
                float2 v = *(const float2*)(xb + r * 64 + c);
                px[2 * it] = v.x; px[2 * it + 1] = v.y;
            }
        }
        for (int i = 0; i < 8; i++) {
            if (i > 0) __syncthreads();          // prior MMA done reading A
            #pragma unroll
            for (int it = 0; it < 8; it++) {     // stage tile i into A (split)
                int idx = t + it * NT;
                int r = idx >> 5, c = (idx & 31) * 2;
                uint32_t hi, lo;
                split2(px[2 * it], px[2 * it + 1], hi, lo);
                *(uint32_t*)&Ahi[r * PITCHA + c] = hi;
                *(uint32_t*)&Alo[r * PITCHA + c] = lo;
            }
            __syncthreads();                     // A (and, for i==0, Bpk) visible
            if (i < 7) {                         // prefetch tile i+1
                const float* xb = x + (size_t)(((i + 1) * NB + b) * TM) * 64;
                #pragma unroll
                for (int it = 0; it < 8; it++) {
                    int idx = t + it * NT;
                    int r = idx >> 5, c = (idx & 31) * 2;
                    float2 v = *(const float2*)(xb + r * 64 + c);
                    px[2 * it] = v.x; px[2 * it + 1] = v.y;
                }
            }
            float acc[4][4];
            #pragma unroll
            for (int j = 0; j < 4; j++)
                #pragma unroll
                for (int q = 0; q < 4; q++) acc[j][q] = 0.f;
            #pragma unroll
            for (int s = 0; s < 4; s++) MMA_KSTEP(s, 0, 1);   // W_r hi/lo

            float* ob = out + (size_t)((i * NB + b) * TM + 16 * mg + g) * 64;
            #pragma unroll
            for (int j = 0; j < 4; j++) {
                int colb = 32 * ng + 8 * j + 2 * tig;
                *(float2*)(ob + colb)          = make_float2(acc[j][0], acc[j][1]);
                *(float2*)(ob + 8 * 64 + colb) = make_float2(acc[j][2], acc[j][3]);
            }
        }
    }
    grid_barrier();   // all xWr visible chip-wide

    // =================== PHASE 2: levels 1..7 recursion ===================
    for (int level = 1; level < NLVL; level++) {
        const int rowbase = level * NPL + b * TM;

        asm volatile("cp.async.wait_group 0;" ::: "memory");
        __syncthreads();   // idx buffer visible; prior MMA done with A smem

        // ---- gather: sum 8 children rows (prev level, L2) into A cols [0,64) ----
        {
            const int4* idxp = (const int4*)(smem + OFF_IDX + (level & 1) * 4096);
            const int col2 = 2 * lane;
            #pragma unroll 4
            for (int rr = 0; rr < 8; rr++) {
                int r = w * 8 + rr;
                int4 c0 = idxp[r * 2];
                int4 c1 = idxp[r * 2 + 1];
                float a0 = 0.f, a1 = 0.f;
                float2 v;
                v = *(const float2*)(out + (size_t)c0.x * 64 + col2); a0 += v.x; a1 += v.y;
                v = *(const float2*)(out + (size_t)c0.y * 64 + col2); a0 += v.x; a1 += v.y;
                v = *(const float2*)(out + (size_t)c0.z * 64 + col2); a0 += v.x; a1 += v.y;
                v = *(const float2*)(out + (size_t)c0.w * 64 + col2); a0 += v.x; a1 += v.y;
                v = *(const float2*)(out + (size_t)c1.x * 64 + col2); a0 += v.x; a1 += v.y;
                v = *(const float2*)(out + (size_t)c1.y * 64 + col2); a0 += v.x; a1 += v.y;
                v = *(const float2*)(out + (size_t)c1.z * 64 + col2); a0 += v.x; a1 += v.y;
                v = *(const float2*)(out + (size_t)c1.w * 64 + col2); a0 += v.x; a1 += v.y;
                uint32_t hi, lo;
                split2(a0, a1, hi, lo);
                *(uint32_t*)&Ahi[r * PITCHA + col2] = hi;
                *(uint32_t*)&Alo[r * PITCHA + col2] = lo;
            }
        }

        // ---- prefetch next level's indices + own xWr rows (consumed post-MMA) ----
        if (level < NLVL - 1) {
            if (t < 256) {
                const char* gp = (const char*)(src + (size_t)level * EPL + (size_t)b * TM * 8) + t * 16;
                CP_ASYNC16(sb + OFF_IDX + ((level + 1) & 1) * 4096 + t * 16, gp);
            }
            asm volatile("cp.async.commit_group;" ::: "memory");
        }
        float2 xwr0[4], xwr1[4];
        {
            const float* xp = out + (size_t)(rowbase + 16 * mg + g) * 64;
            #pragma unroll
            for (int j = 0; j < 4; j++) {
                int colb = 32 * ng + 8 * j + 2 * tig;
                xwr0[j] = *(const float2*)(xp + colb);
                xwr1[j] = *(const float2*)(xp + 8 * 64 + colb);
            }
        }
        __syncthreads();   // gather results visible for MMA

        // ---- accumulators: bias folded in ----
        float acc[4][4];
        #pragma unroll
        for (int j = 0; j < 4; j++) {
            float b0 = bls[32 * ng + 8 * j + 2 * tig];
            float b1 = bls[32 * ng + 8 * j + 2 * tig + 1];
            acc[j][0] = b0; acc[j][1] = b1; acc[j][2] = b0; acc[j][3] = b1;
        }

        // ---- MMA: agg @ W_l^T, 3-term split, K=64 ----
        #pragma unroll
        for (int s = 0; s < 4; s++) MMA_KSTEP(s, 2, 3);       // W_l hi/lo

        // ---- epilogue: tanh(acc + xWr) ----
        {
            float* ob = out + (size_t)(rowbase + 16 * mg + g) * 64;
            #pragma unroll
            for (int j = 0; j < 4; j++) {
                int colb = 32 * ng + 8 * j + 2 * tig;
                float2 p0 = make_float2(tanh_fast(acc[j][0] + xwr0[j].x),
                                        tanh_fast(acc[j][1] + xwr0[j].y));
                float2 p1 = make_float2(tanh_fast(acc[j][2] + xwr1[j].x),
                                        tanh_fast(acc[j][3] + xwr1[j].y));
                *(float2*)(ob + colb)          = p0;
                *(float2*)(ob + 8 * 64 + colb) = p1;
            }
        }

        if (level < NLVL - 1) grid_barrier();
    }
}

extern "C" void kernel_launch(void* const* d_in, const int* in_sizes, int n_in,
                              void* d_out, int out_size)
{
    const float* x   = (const float*)d_in[0];
    const int*   ei  = (const int*)  d_in[1];   // row 0 = src
    const float* Wl  = (const float*)d_in[2];
    const float* bl  = (const float*)d_in[3];
    const float* Wr  = (const float*)d_in[4];
    float*       out = (float*)d_out;

    cudaFuncSetAttribute(dag_mma, cudaFuncAttributeMaxDynamicSharedMemorySize, SMEM_BYTES);
    dag_mma<<<NB, NT, SMEM_BYTES>>>(x, ei, Wl, bl, Wr, out);
}

// round 12
// speedup vs baseline: 1.0652x; 1.0652x over previous
#include <cuda_runtime.h>
#include <cuda_bf16.h>
#include <cstdint>

#define NPL   16384
#define NLVL  8
#define EPL   (NPL * 8)
#define TM    64            // rows per block tile
#define NB    256           // persistent grid, 2 CTAs/SM (all co-resident)
#define NT    256           // 8 warps
#define PITCHA 136          // bf16 elems per A row -> conflict-free ldmatrix

// smem byte offsets
#define OFF_AHI 0                        // 64 x 136 bf16 = 17408 B
#define OFF_ALO 17408
#define OFF_BPK 34816                    // 2 mats x 8 ksteps x 8 ntiles x 32 x uint2 = 32768 B
#define OFF_BL  67584                    // 64 floats
#define OFF_IDX 67840                    // 2 x 2048 B index double buffer
#define SMEM_BYTES (OFF_IDX + 4096)      // 71936 B -> 2 CTAs/SM fit (144 KB)

__device__ unsigned int g_count = 0;
__device__ unsigned int g_phase = 0;

__device__ __forceinline__ void grid_barrier() {
    __threadfence();
    __syncthreads();
    if (threadIdx.x == 0) {
        volatile unsigned int* ph = &g_phase;
        unsigned int my = *ph;
        unsigned int v = atomicAdd(&g_count, 1u);
        if (v == NB - 1) {
            atomicExch(&g_count, 0u);
            __threadfence();
            atomicAdd(&g_phase, 1u);
        } else {
            while (*ph == my) { }
        }
    }
    __syncthreads();
}

__device__ __forceinline__ float tanh_fast(float v) {
    v = fminf(fmaxf(v, -20.0f), 20.0f);
    float e;
    asm("ex2.approx.f32 %0, %1;" : "=f"(e) : "f"(v * 2.8853900817779268f)); // exp(2v)
    float r;
    asm("rcp.approx.f32 %0, %1;" : "=f"(r) : "f"(e + 1.0f));
    return (e - 1.0f) * r;
}

__device__ __forceinline__ uint32_t smem_u32(const void* p) {
    uint32_t a;
    asm("{ .reg .u64 t; cvta.to.shared.u64 t, %1; cvt.u32.u64 %0, t; }" : "=r"(a) : "l"(p));
    return a;
}

__device__ __forceinline__ void split2(float a0, float a1, uint32_t& hi, uint32_t& lo) {
    __nv_bfloat162 h = __floats2bfloat162_rn(a0, a1);
    hi = *reinterpret_cast<uint32_t*>(&h);
    float r0 = a0 - __bfloat162float(h.x);
    float r1 = a1 - __bfloat162float(h.y);
    __nv_bfloat162 l = __floats2bfloat162_rn(r0, r1);
    lo = *reinterpret_cast<uint32_t*>(&l);
}

#define CP_ASYNC16(saddr, gptr) \
    asm volatile("cp.async.cg.shared.global [%0], [%1], 16;" :: "r"(saddr), "l"(gptr))

#define LDSM4(a0, a1, a2, a3, addr)                                              \
    asm volatile("ldmatrix.sync.aligned.m8n8.x4.shared.b16 {%0,%1,%2,%3}, [%4];" \
                 : "=r"(a0), "=r"(a1), "=r"(a2), "=r"(a3) : "r"(addr))

#define MMA(accj, a0, a1, a2, a3, b0, b1)                                        \
    asm volatile("mma.sync.aligned.m16n8k16.row.col.f32.bf16.bf16.f32 "          \
                 "{%0,%1,%2,%3}, {%4,%5,%6,%7}, {%8,%9}, {%0,%1,%2,%3};"         \
                 : "+f"(accj[0]), "+f"(accj[1]), "+f"(accj[2]), "+f"(accj[3])    \
                 : "r"(a0), "r"(a1), "r"(a2), "r"(a3), "r"(b0), "r"(b1))

#define MMA_STEP(abase, mat, k0) do {                                            \
    uint32_t a0, a1, a2, a3;                                                     \
    LDSM4(a0, a1, a2, a3, (abase) + (uint32_t)(k0) * 2u);                        \
    const uint2* bp = Bpk + (((size_t)(mat) * 8 + ((k0) >> 4)) * 8 + 4 * ng) * 32 + lane; \
    uint2 bb0 = bp[0];                                                           \
    uint2 bb1 = bp[32];                                                          \
    uint2 bb2 = bp[64];                                                          \
    uint2 bb3 = bp[96];                                                          \
    MMA(acc[0], a0, a1, a2, a3, bb0.x, bb0.y);                                   \
    MMA(acc[1], a0, a1, a2, a3, bb1.x, bb1.y);                                   \
    MMA(acc[2], a0, a1, a2, a3, bb2.x, bb2.y);                                   \
    MMA(acc[3], a0, a1, a2, a3, bb3.x, bb3.y);                                   \
} while (0)

__global__ void __launch_bounds__(NT, 2)
dag_mma(const float* __restrict__ x,
        const int*   __restrict__ src,
        const float* __restrict__ Wl,
        const float* __restrict__ bl,
        const float* __restrict__ Wr,
        float*       __restrict__ out)
{
    extern __shared__ char smem[];
    __nv_bfloat16* Ahi  = (__nv_bfloat16*)(smem + OFF_AHI);
    __nv_bfloat16* Alo  = (__nv_bfloat16*)(smem + OFF_ALO);
    const uint2*   Bpk  = (const uint2*)(smem + OFF_BPK);
    uint2*         BpkW = (uint2*)(smem + OFF_BPK);
    float*         bls  = (float*)(smem + OFF_BL);
    const uint32_t sb   = smem_u32(smem);

    const int t    = threadIdx.x;
    const int b    = blockIdx.x;
    const int lane = t & 31;
    const int w    = t >> 5;        // warp 0..7
    const int tig  = lane & 3;
    const int g    = lane >> 2;
    const int mg   = w >> 1;        // rows 16mg..16mg+15 (0..3)
    const int ng   = w & 1;         // cols 32ng..32ng+31

    // ---- one-time: prepack B fragments (hi & lo) + bias ----
    {
        #pragma unroll
        for (int it = 0; it < 16; it++) {
            int idx  = t + it * NT;          // 0..4095
            int ln   = idx & 31;
            int tile = idx >> 5;             // 0..127
            int mat  = tile >> 6;            // 0 = hi, 1 = lo
            int s    = (tile >> 3) & 7;      // kstep 0..7
            int j    = tile & 7;             // n-tile 0..7
            int n    = 8 * j + (ln >> 2);
            int k0   = 16 * s + 2 * (ln & 3);
            auto Wsrc = [&](int kk) {
                return (kk < 64) ? Wr[n * 64 + kk] : Wl[n * 64 + kk - 64];
            };
            float v00 = Wsrc(k0),     v01 = Wsrc(k0 + 1);
            float v10 = Wsrc(k0 + 8), v11 = Wsrc(k0 + 9);
            uint32_t h0, l0, h1, l1;
            split2(v00, v01, h0, l0);
            split2(v10, v11, h1, l1);
            BpkW[(size_t)tile * 32 + ln] = (mat == 0) ? make_uint2(h0, h1) : make_uint2(l0, l1);
        }
        if (t < 64) bls[t] = bl[t];
    }

    // ---- stage level-0 x into A cols [0,64) ----
    {
        const float* xb = x + (size_t)(b * TM) * 64;
        #pragma unroll
        for (int it = 0; it < 8; it++) {
            int idx = t + it * NT;           // 0..2047
            int r = idx >> 5, c = (idx & 31) * 2;
            float2 v = *(const float2*)(xb + r * 64 + c);
            uint32_t hi, lo;
            split2(v.x, v.y, hi, lo);
            *(uint32_t*)&Ahi[r * PITCHA + c] = hi;
            *(uint32_t*)&Alo[r * PITCHA + c] = lo;
        }
    }

    // ---- prefetch level-1 edge indices (TM*8*4 = 2048 B) ----
    if (t < 128) {
        const char* gp = (const char*)(src + (size_t)b * TM * 8) + t * 16;
        CP_ASYNC16(sb + OFF_IDX + 2048 + t * 16, gp);
    }
    asm volatile("cp.async.commit_group;" ::: "memory");
    __syncthreads();

    const int row_l = lane & 15;
    const int kof   = (lane >> 4) << 3;
    const uint32_t aHiBase = sb + OFF_AHI + (uint32_t)((16 * mg + row_l) * PITCHA + kof) * 2u;
    const uint32_t aLoBase = sb + OFF_ALO + (uint32_t)((16 * mg + row_l) * PITCHA + kof) * 2u;

    float px[16];

    for (int level = 0; level < NLVL; level++) {
        const int rowbase = level * NPL + b * TM;

        // ---- gather: idx from smem, data from L2; warp-local rows ----
        if (level > 0) {
            asm volatile("cp.async.wait_group 0;" ::: "memory");
            __syncthreads();
            const int4* idxp = (const int4*)(smem + OFF_IDX + (level & 1) * 2048);
            const int col2 = 2 * lane;
            #pragma unroll 4
            for (int rr = 0; rr < 8; rr++) {
                int r = w * 8 + rr;
                int4 c0 = idxp[r * 2];
                int4 c1 = idxp[r * 2 + 1];
                float a0 = 0.f, a1 = 0.f;
                float2 v;
                v = *(const float2*)(out + (size_t)c0.x * 64 + col2); a0 += v.x; a1 += v.y;
                v = *(const float2*)(out + (size_t)c0.y * 64 + col2); a0 += v.x; a1 += v.y;
                v = *(const float2*)(out + (size_t)c0.z * 64 + col2); a0 += v.x; a1 += v.y;
                v = *(const float2*)(out + (size_t)c0.w * 64 + col2); a0 += v.x; a1 += v.y;
                v = *(const float2*)(out + (size_t)c1.x * 64 + col2); a0 += v.x; a1 += v.y;
                v = *(const float2*)(out + (size_t)c1.y * 64 + col2); a0 += v.x; a1 += v.y;
                v = *(const float2*)(out + (size_t)c1.z * 64 + col2); a0 += v.x; a1 += v.y;
                v = *(const float2*)(out + (size_t)c1.w * 64 + col2); a0 += v.x; a1 += v.y;
                uint32_t hi, lo;
                split2(a0, a1, hi, lo);
                *(uint32_t*)&Ahi[r * PITCHA + 64 + col2] = hi;
                *(uint32_t*)&Alo[r * PITCHA + 64 + col2] = lo;
            }
        }

        // ---- prefetch next level's indices + x rows ----
        if (level < NLVL - 1) {
            if (t < 128) {
                const char* gp = (const char*)(src + (size_t)level * EPL + (size_t)b * TM * 8) + t * 16;
                CP_ASYNC16(sb + OFF_IDX + ((level + 1) & 1) * 2048 + t * 16, gp);
            }
            asm volatile("cp.async.commit_group;" ::: "memory");

            const float* xb = x + (size_t)((level + 1) * NPL + b * TM) * 64;
            #pragma unroll
            for (int it = 0; it < 8; it++) {
                int idx = t + it * NT;
                int r = idx >> 5, c = (idx & 31) * 2;
                float2 v = *(const float2*)(xb + r * 64 + c);
                px[2 * it]     = v.x;
                px[2 * it + 1] = v.y;
            }
        }
        __syncthreads();   // gather results visible for MMA

        // ---- accumulators (bias folded in for levels > 0) ----
        float acc[4][4];
        if (level == 0) {
            #pragma unroll
            for (int j = 0; j < 4; j++)
                #pragma unroll
                for (int q = 0; q < 4; q++) acc[j][q] = 0.f;
        } else {
            #pragma unroll
            for (int j = 0; j < 4; j++) {
                float b0 = bls[32 * ng + 8 * j + 2 * tig];
                float b1 = bls[32 * ng + 8 * j + 2 * tig + 1];
                acc[j][0] = b0; acc[j][1] = b1; acc[j][2] = b0; acc[j][3] = b1;
            }
        }

        // ---- MMA: 3-term bf16 split ----
        #pragma unroll
        for (int s4 = 0; s4 < 4; s4++) MMA_STEP(aHiBase, 0, 16 * s4);
        #pragma unroll
        for (int s4 = 0; s4 < 4; s4++) MMA_STEP(aHiBase, 1, 16 * s4);
        #pragma unroll
        for (int s4 = 0; s4 < 4; s4++) MMA_STEP(aLoBase, 0, 16 * s4);
        if (level > 0) {
            #pragma unroll
            for (int s4 = 0; s4 < 4; s4++) MMA_STEP(aHiBase, 0, 64 + 16 * s4);
            #pragma unroll
            for (int s4 = 0; s4 < 4; s4++) MMA_STEP(aHiBase, 1, 64 + 16 * s4);
            #pragma unroll
            for (int s4 = 0; s4 < 4; s4++) MMA_STEP(aLoBase, 0, 64 + 16 * s4);
        }

        // ---- epilogue ----
        {
            float* ob = out + (size_t)(rowbase + 16 * mg + g) * 64;
            #pragma unroll
            for (int j = 0; j < 4; j++) {
                int colb = 32 * ng + 8 * j + 2 * tig;
                float2 p0, p1;
                if (level == 0) {
                    p0 = make_float2(acc[j][0], acc[j][1]);
                    p1 = make_float2(acc[j][2], acc[j][3]);
                } else {
                    p0 = make_float2(tanh_fast(acc[j][0]), tanh_fast(acc[j][1]));
                    p1 = make_float2(tanh_fast(acc[j][2]), tanh_fast(acc[j][3]));
                }
                *(float2*)(ob + colb)          = p0;
                *(float2*)(ob + 8 * 64 + colb) = p1;
            }
        }

        if (level < NLVL - 1) {
            grid_barrier();
            // stage prefetched x for next level
            #pragma unroll
            for (int it = 0; it < 8; it++) {
                int idx = t + it * NT;
                int r = idx >> 5, c = (idx & 31) * 2;
                uint32_t hi, lo;
                split2(px[2 * it], px[2 * it + 1], hi, lo);
                *(uint32_t*)&Ahi[r * PITCHA + c] = hi;
                *(uint32_t*)&Alo[r * PITCHA + c] = lo;
            }
        }
    }
}

extern "C" void kernel_launch(void* const* d_in, const int* in_sizes, int n_in,
                              void* d_out, int out_size)
{
    const float* x   = (const float*)d_in[0];
    const int*   ei  = (const int*)  d_in[1];   // row 0 = src
    const float* Wl  = (const float*)d_in[2];
    const float* bl  = (const float*)d_in[3];
    const float* Wr  = (const float*)d_in[4];
    float*       out = (float*)d_out;

    cudaFuncSetAttribute(dag_mma, cudaFuncAttributeMaxDynamicSharedMemorySize, SMEM_BYTES);
    dag_mma<<<NB, NT, SMEM_BYTES>>>(x, ei, Wl, bl, Wr, out);
}

// round 13
// speedup vs baseline: 1.1436x; 1.0735x over previous
#include <cuda_runtime.h>
#include <cuda_bf16.h>
#include <cstdint>

#define NPL   16384
#define NLVL  8
#define EPL   (NPL * 8)
#define TM    64            // rows per block tile
#define NB    256           // persistent grid, 2 CTAs/SM (all co-resident)
#define NT    256           // 8 warps; pair p = warps {2p,2p+1} owns rows 16p..16p+15
#define NWARPS_TOTAL (NB * 8)
#define PITCHA 136          // bf16 elems per A row -> conflict-free ldmatrix

// smem byte offsets
#define OFF_AHI 0                        // 64 x 136 bf16 = 17408 B
#define OFF_ALO 17408
#define OFF_BPK 34816                    // 2 x 8 x 8 x 32 x uint2 = 32768 B
#define OFF_BL  67584                    // 64 floats
#define OFF_IDX 67840                    // 2 x 2048 B index double buffer
#define SMEM_BYTES (OFF_IDX + 4096)      // 71936 B -> 2 CTAs/SM

__device__ unsigned int g_count = 0;
__device__ unsigned int g_phase = 0;

__device__ __forceinline__ float tanh_fast(float v) {
    v = fminf(fmaxf(v, -20.0f), 20.0f);
    float e;
    asm("ex2.approx.f32 %0, %1;" : "=f"(e) : "f"(v * 2.8853900817779268f)); // exp(2v)
    float r;
    asm("rcp.approx.f32 %0, %1;" : "=f"(r) : "f"(e + 1.0f));
    return (e - 1.0f) * r;
}

__device__ __forceinline__ uint32_t smem_u32(const void* p) {
    uint32_t a;
    asm("{ .reg .u64 t; cvta.to.shared.u64 t, %1; cvt.u32.u64 %0, t; }" : "=r"(a) : "l"(p));
    return a;
}

__device__ __forceinline__ void split2(float a0, float a1, uint32_t& hi, uint32_t& lo) {
    __nv_bfloat162 h = __floats2bfloat162_rn(a0, a1);
    hi = *reinterpret_cast<uint32_t*>(&h);
    float r0 = a0 - __bfloat162float(h.x);
    float r1 = a1 - __bfloat162float(h.y);
    __nv_bfloat162 l = __floats2bfloat162_rn(r0, r1);
    lo = *reinterpret_cast<uint32_t*>(&l);
}

#define CP_ASYNC16(saddr, gptr) \
    asm volatile("cp.async.cg.shared.global [%0], [%1], 16;" :: "r"(saddr), "l"(gptr))
#define PAIR_BAR(p) \
    asm volatile("bar.sync %0, 64;" :: "r"(1 + (p)) : "memory")

#define LDSM4(a0, a1, a2, a3, addr)                                              \
    asm volatile("ldmatrix.sync.aligned.m8n8.x4.shared.b16 {%0,%1,%2,%3}, [%4];" \
                 : "=r"(a0), "=r"(a1), "=r"(a2), "=r"(a3) : "r"(addr))

#define MMA(accj, a0, a1, a2, a3, b0, b1)                                        \
    asm volatile("mma.sync.aligned.m16n8k16.row.col.f32.bf16.bf16.f32 "          \
                 "{%0,%1,%2,%3}, {%4,%5,%6,%7}, {%8,%9}, {%0,%1,%2,%3};"         \
                 : "+f"(accj[0]), "+f"(accj[1]), "+f"(accj[2]), "+f"(accj[3])    \
                 : "r"(a0), "r"(a1), "r"(a2), "r"(a3), "r"(b0), "r"(b1))

#define MMA_STEP(abase, mat, k0) do {                                            \
    uint32_t a0, a1, a2, a3;                                                     \
    LDSM4(a0, a1, a2, a3, (abase) + (uint32_t)(k0) * 2u);                        \
    const uint2* bp = Bpk + (((size_t)(mat) * 8 + ((k0) >> 4)) * 8 + 4 * ng) * 32 + lane; \
    uint2 bb0 = bp[0];                                                           \
    uint2 bb1 = bp[32];                                                          \
    uint2 bb2 = bp[64];                                                          \
    uint2 bb3 = bp[96];                                                          \
    MMA(acc[0], a0, a1, a2, a3, bb0.x, bb0.y);                                   \
    MMA(acc[1], a0, a1, a2, a3, bb1.x, bb1.y);                                   \
    MMA(acc[2], a0, a1, a2, a3, bb2.x, bb2.y);                                   \
    MMA(acc[3], a0, a1, a2, a3, bb3.x, bb3.y);                                   \
} while (0)

__global__ void __launch_bounds__(NT, 2)
dag_mma(const float* __restrict__ x,
        const int*   __restrict__ src,
        const float* __restrict__ Wl,
        const float* __restrict__ bl,
        const float* __restrict__ Wr,
        float*       __restrict__ out)
{
    extern __shared__ char smem[];
    __nv_bfloat16* Ahi  = (__nv_bfloat16*)(smem + OFF_AHI);
    __nv_bfloat16* Alo  = (__nv_bfloat16*)(smem + OFF_ALO);
    const uint2*   Bpk  = (const uint2*)(smem + OFF_BPK);
    uint2*         BpkW = (uint2*)(smem + OFF_BPK);
    float*         bls  = (float*)(smem + OFF_BL);
    const uint32_t sb   = smem_u32(smem);

    const int t    = threadIdx.x;
    const int b    = blockIdx.x;
    const int lane = t & 31;
    const int w    = t >> 5;        // warp 0..7
    const int p    = w >> 1;        // pair 0..3, rows 16p..16p+15
    const int tig  = lane & 3;
    const int g    = lane >> 2;
    const int ng   = w & 1;
    const int ptid = ((w & 1) << 5) | lane;    // 0..63 within pair

    // ---- one-time: prepack B fragments + bias ----
    {
        #pragma unroll
        for (int it = 0; it < 16; it++) {
            int idx  = t + it * NT;
            int ln   = idx & 31;
            int tile = idx >> 5;
            int mat  = tile >> 6;
            int s    = (tile >> 3) & 7;
            int j    = tile & 7;
            int n    = 8 * j + (ln >> 2);
            int k0   = 16 * s + 2 * (ln & 3);
            auto Wsrc = [&](int kk) {
                return (kk < 64) ? Wr[n * 64 + kk] : Wl[n * 64 + kk - 64];
            };
            float v00 = Wsrc(k0),     v01 = Wsrc(k0 + 1);
            float v10 = Wsrc(k0 + 8), v11 = Wsrc(k0 + 9);
            uint32_t h0, l0, h1, l1;
            split2(v00, v01, h0, l0);
            split2(v10, v11, h1, l1);
            BpkW[(size_t)tile * 32 + ln] = (mat == 0) ? make_uint2(h0, h1) : make_uint2(l0, l1);
        }
        if (t < 64) bls[t] = bl[t];
    }

    // ---- stage level-0 x ----
    {
        const float* xb = x + (size_t)(b * TM) * 64;
        #pragma unroll
        for (int it = 0; it < 8; it++) {
            int idx = t + it * NT;
            int r = idx >> 5, c = (idx & 31) * 2;
            float2 v = *(const float2*)(xb + r * 64 + c);
            uint32_t hi, lo;
            split2(v.x, v.y, hi, lo);
            *(uint32_t*)&Ahi[r * PITCHA + c] = hi;
            *(uint32_t*)&Alo[r * PITCHA + c] = lo;
        }
    }

    // ---- prefetch level-1 idx: each warp its own 256 B chunk ----
    if (lane < 16) {
        const char* gp = (const char*)(src + (size_t)(b * TM + w * 8) * 8) + lane * 16;
        CP_ASYNC16(sb + OFF_IDX + 2048 + w * 256 + lane * 16, gp);
    }
    asm volatile("cp.async.commit_group;" ::: "memory");
    __syncthreads();

    const int row_l = lane & 15;
    const int kof   = (lane >> 4) << 3;
    const uint32_t aHiBase = sb + OFF_AHI + (uint32_t)((16 * p + row_l) * PITCHA + kof) * 2u;
    const uint32_t aLoBase = sb + OFF_ALO + (uint32_t)((16 * p + row_l) * PITCHA + kof) * 2u;

    float px[16];

    for (int level = 0; level < NLVL; level++) {
        const int rowbase = level * NPL + b * TM;

        // ---- gather (warp-local rows w*8..w*8+7) ----
        if (level > 0) {
            asm volatile("cp.async.wait_group 0;" ::: "memory");
            __syncwarp();
            const int4* idxp = (const int4*)(smem + OFF_IDX + (level & 1) * 2048);
            const int col2 = 2 * lane;
            #pragma unroll 4
            for (int rr = 0; rr < 8; rr++) {
                int r = w * 8 + rr;
                int4 c0 = idxp[r * 2];
                int4 c1 = idxp[r * 2 + 1];
                float a0 = 0.f, a1 = 0.f;
                float2 v;
                v = *(const float2*)(out + (size_t)c0.x * 64 + col2); a0 += v.x; a1 += v.y;
                v = *(const float2*)(out + (size_t)c0.y * 64 + col2); a0 += v.x; a1 += v.y;
                v = *(const float2*)(out + (size_t)c0.z * 64 + col2); a0 += v.x; a1 += v.y;
                v = *(const float2*)(out + (size_t)c0.w * 64 + col2); a0 += v.x; a1 += v.y;
                v = *(const float2*)(out + (size_t)c1.x * 64 + col2); a0 += v.x; a1 += v.y;
                v = *(const float2*)(out + (size_t)c1.y * 64 + col2); a0 += v.x; a1 += v.y;
                v = *(const float2*)(out + (size_t)c1.z * 64 + col2); a0 += v.x; a1 += v.y;
                v = *(const float2*)(out + (size_t)c1.w * 64 + col2); a0 += v.x; a1 += v.y;
                uint32_t hi, lo;
                split2(a0, a1, hi, lo);
                *(uint32_t*)&Ahi[r * PITCHA + 64 + col2] = hi;
                *(uint32_t*)&Alo[r * PITCHA + 64 + col2] = lo;
            }
        }

        // ---- prefetch next level's idx (own chunk) + x rows (pair slots) ----
        if (level < NLVL - 1) {
            if (lane < 16) {
                const char* gp = (const char*)(src + (size_t)level * EPL
                                               + (size_t)(b * TM + w * 8) * 8) + lane * 16;
                CP_ASYNC16(sb + OFF_IDX + ((level + 1) & 1) * 2048 + w * 256 + lane * 16, gp);
            }
            asm volatile("cp.async.commit_group;" ::: "memory");

            const float* xb = x + (size_t)((level + 1) * NPL + b * TM + 16 * p) * 64;
            #pragma unroll
            for (int it = 0; it < 8; it++) {
                int idx = ptid + it * 64;        // 0..511 within pair
                int rl = idx >> 5, c = (idx & 31) * 2;
                float2 v = *(const float2*)(xb + rl * 64 + c);
                px[2 * it]     = v.x;
                px[2 * it + 1] = v.y;
            }
        }

        PAIR_BAR(p);   // pair's A rows (x from prev staging + this gather) ready

        // ---- accumulators ----
        float acc[4][4];
        if (level == 0) {
            #pragma unroll
            for (int j = 0; j < 4; j++)
                #pragma unroll
                for (int q = 0; q < 4; q++) acc[j][q] = 0.f;
        } else {
            #pragma unroll
            for (int j = 0; j < 4; j++) {
                float b0 = bls[32 * ng + 8 * j + 2 * tig];
                float b1 = bls[32 * ng + 8 * j + 2 * tig + 1];
                acc[j][0] = b0; acc[j][1] = b1; acc[j][2] = b0; acc[j][3] = b1;
            }
        }

        // ---- MMA: 3-term bf16 split ----
        #pragma unroll
        for (int s4 = 0; s4 < 4; s4++) MMA_STEP(aHiBase, 0, 16 * s4);
        #pragma unroll
        for (int s4 = 0; s4 < 4; s4++) MMA_STEP(aHiBase, 1, 16 * s4);
        #pragma unroll
        for (int s4 = 0; s4 < 4; s4++) MMA_STEP(aLoBase, 0, 16 * s4);
        if (level > 0) {
            #pragma unroll
            for (int s4 = 0; s4 < 4; s4++) MMA_STEP(aHiBase, 0, 64 + 16 * s4);
            #pragma unroll
            for (int s4 = 0; s4 < 4; s4++) MMA_STEP(aHiBase, 1, 64 + 16 * s4);
            #pragma unroll
            for (int s4 = 0; s4 < 4; s4++) MMA_STEP(aLoBase, 0, 64 + 16 * s4);
        }

        // ---- epilogue ----
        {
            float* ob = out + (size_t)(rowbase + 16 * p + g) * 64;
            #pragma unroll
            for (int j = 0; j < 4; j++) {
                int colb = 32 * ng + 8 * j + 2 * tig;
                float2 p0, p1;
                if (level == 0) {
                    p0 = make_float2(acc[j][0], acc[j][1]);
                    p1 = make_float2(acc[j][2], acc[j][3]);
                } else {
                    p0 = make_float2(tanh_fast(acc[j][0]), tanh_fast(acc[j][1]));
                    p1 = make_float2(tanh_fast(acc[j][2]), tanh_fast(acc[j][3]));
                }
                *(float2*)(ob + colb)          = p0;
                *(float2*)(ob + 8 * 64 + colb) = p1;
            }
        }

        if (level < NLVL - 1) {
            // ---- warp-granular arrival ----
            __syncwarp();
            __threadfence();
            unsigned my = 0;
            if (lane == 0) {
                my = *(volatile unsigned int*)&g_phase;     // read BEFORE arriving
                unsigned old = atomicAdd(&g_count, 1u);
                if (old == NWARPS_TOTAL - 1) {
                    atomicExch(&g_count, 0u);
                    __threadfence();
                    atomicAdd(&g_phase, 1u);
                }
            }

            PAIR_BAR(p);   // partner's MMA done reading A x-cols

            // ---- stage next level's x into pair rows (hidden in barrier wait) ----
            #pragma unroll
            for (int it = 0; it < 8; it++) {
                int idx = ptid + it * 64;
                int rl = idx >> 5, c = (idx & 31) * 2;
                uint32_t hi, lo;
                split2(px[2 * it], px[2 * it + 1], hi, lo);
                *(uint32_t*)&Ahi[(16 * p + rl) * PITCHA + c] = hi;
                *(uint32_t*)&Alo[(16 * p + rl) * PITCHA + c] = lo;
            }

            // ---- release: warp 0 polls, block-wide wait ----
            if (w == 0 && lane == 0) {
                volatile unsigned int* ph = &g_phase;
                while (*ph == my) { __nanosleep(64); }
            }
            __syncthreads();
        }
    }
}

extern "C" void kernel_launch(void* const* d_in, const int* in_sizes, int n_in,
                              void* d_out, int out_size)
{
    const float* x   = (const float*)d_in[0];
    const int*   ei  = (const int*)  d_in[1];   // row 0 = src
    const float* Wl  = (const float*)d_in[2];
    const float* bl  = (const float*)d_in[3];
    const float* Wr  = (const float*)d_in[4];
    float*       out = (float*)d_out;

    cudaFuncSetAttribute(dag_mma, cudaFuncAttributeMaxDynamicSharedMemorySize, SMEM_BYTES);
    dag_mma<<<NB, NT, SMEM_BYTES>>>(x, ei, Wl, bl, Wr, out);
}